// round 16
// baseline (speedup 1.0000x reference)
#include <cuda_runtime.h>
#include <cuda_fp16.h>

#define NN 50000
#define NE 1600000
#define NEG 0.2f
#define W 128           // ELL width (in-degree is Poisson(32); max ~65)
#define NOVF 65536      // overflow insurance capacity

// ---------------- scratch (device globals; no allocation allowed) ----------
// g_deg/g_novf are zero at module load and re-zeroed by kagg's tail each run.
__device__ float4 g_hq[NN];          // per-node h_q (4 heads)
__device__ float4 g_kact[NN];        // per-node leaky(x@Wk^T)
__device__ float4 g_qagg[NN];        // per-node aggregated q
__device__ float  g_hproj[NN * 128]; // per-node x@Wl^T + bl (fp32)
__device__ float  g_w[NN * W];       // per-edge mean-softmax weight (ELL layout)
__device__ float4 g_m[NN];           // per-node maxes   (insurance only)
__device__ float4 g_is[NN];          // per-node inv-sums (insurance only)
__device__ int    g_deg[NN];
__device__ int    g_ell[NN * W];     // ELL adjacency: cols of incoming edges
__device__ int    g_ovf_r[NOVF];
__device__ int    g_ovf_c[NOVF];
__device__ int    g_novf;

// ---------------- kbig: fused gemm + build + proj --------------------------
#define GB ((NN + 127) / 128)            // 391 gemm blocks
#define BB ((NE / 16 + 255) / 256)       // 391 build blocks
#define PB ((NN * 32 + 255) / 256)       // 6250 proj blocks
#define XS_STRIDE 72
__global__ __launch_bounds__(256) void kbig(const float* __restrict__ x,
                                            const float* __restrict__ Wq,
                                            const float* __restrict__ Wk,
                                            const float* __restrict__ Wl,
                                            const float* __restrict__ bl,
                                            const int* __restrict__ ei) {
    __shared__ __half xs[128 * XS_STRIDE];
    __shared__ __half ws[128 * XS_STRIDE];
    if (blockIdx.x >= GB + BB) {
        // ---- proj branch: h_q, k_act ----
        int bid = blockIdx.x - GB - BB;
        int w = (bid * 256 + threadIdx.x) >> 5;
        int lane = threadIdx.x & 31;
        if (w >= NN) return;
        float4 xv = ((const float4*)x)[w * 32 + lane];
        float a[8];
#pragma unroll
        for (int h = 0; h < 4; h++) {
            float4 q = ((const float4*)Wq)[h * 32 + lane];
            float4 k = ((const float4*)Wk)[h * 32 + lane];
            a[h]     = xv.x * q.x + xv.y * q.y + xv.z * q.z + xv.w * q.w;
            a[4 + h] = xv.x * k.x + xv.y * k.y + xv.z * k.z + xv.w * k.w;
        }
#pragma unroll
        for (int off = 16; off; off >>= 1) {
#pragma unroll
            for (int h = 0; h < 8; h++) a[h] += __shfl_xor_sync(0xffffffffu, a[h], off);
        }
        if (lane == 0) {
            g_hq[w] = make_float4(a[0], a[1], a[2], a[3]);
            float4 kk;
            kk.x = a[4] >= 0.f ? a[4] : NEG * a[4];
            kk.y = a[5] >= 0.f ? a[5] : NEG * a[5];
            kk.z = a[6] >= 0.f ? a[6] : NEG * a[6];
            kk.w = a[7] >= 0.f ? a[7] : NEG * a[7];
            g_kact[w] = kk;
        }
        return;
    }
    if (blockIdx.x >= GB) {
        // ---- build branch: 16 edges/thread (g_deg pre-zeroed invariant) ----
        int t = (blockIdx.x - GB) * 256 + threadIdx.x;
        int e0 = t * 16;
        if (e0 >= NE) return;
        int rr[16], cc[16], pp[16];
#pragma unroll
        for (int v = 0; v < 4; v++) {
            int4 r4 = *(const int4*)&ei[e0 + v * 4];
            int4 c4 = *(const int4*)&ei[NE + e0 + v * 4];
            rr[v * 4 + 0] = r4.x; rr[v * 4 + 1] = r4.y;
            rr[v * 4 + 2] = r4.z; rr[v * 4 + 3] = r4.w;
            cc[v * 4 + 0] = c4.x; cc[v * 4 + 1] = c4.y;
            cc[v * 4 + 2] = c4.z; cc[v * 4 + 3] = c4.w;
        }
#pragma unroll
        for (int j = 0; j < 16; j++) pp[j] = atomicAdd(&g_deg[rr[j]], 1);
#pragma unroll
        for (int j = 0; j < 16; j++) {
            if (pp[j] < W) {
                g_ell[rr[j] * W + pp[j]] = cc[j];
            } else {
                int o = atomicAdd(&g_novf, 1);
                if (o < NOVF) { g_ovf_r[o] = rr[j]; g_ovf_c[o] = cc[j]; }
            }
        }
        return;
    }
    // ---- gemm branch: HMMA fp16-in fp32-acc fp32-store ----
    int nb = blockIdx.x * 128;
    int tid = threadIdx.x;
    int wid = tid >> 5;
    int lane = tid & 31;
    int warp_m = wid & 3;
    int warp_n = wid >> 2;
    int group = lane >> 2;        // 0..7
    int qk = (lane & 3) * 2;      // 0,2,4,6

    float acc[2][8][4];
#pragma unroll
    for (int mi = 0; mi < 2; mi++)
#pragma unroll
        for (int ni = 0; ni < 8; ni++)
#pragma unroll
            for (int r = 0; r < 4; r++) acc[mi][ni][r] = 0.f;

    for (int ko = 0; ko < 2; ko++) {          // two 64-wide K chunks
#pragma unroll
        for (int it = 0; it < 8; it++) {
            int idx = tid + it * 256;          // 0..2047
            int row = idx >> 4, c = idx & 15;
            float4 v = make_float4(0.f, 0.f, 0.f, 0.f);
            if (nb + row < NN) v = ((const float4*)x)[(nb + row) * 32 + ko * 16 + c];
            __half2 h01 = __floats2half2_rn(v.x, v.y);
            __half2 h23 = __floats2half2_rn(v.z, v.w);
            uint2 pk = make_uint2(*(unsigned*)&h01, *(unsigned*)&h23);
            *(uint2*)&xs[row * XS_STRIDE + c * 4] = pk;
            float4 wv = ((const float4*)Wl)[row * 32 + ko * 16 + c];
            __half2 w01 = __floats2half2_rn(wv.x, wv.y);
            __half2 w23 = __floats2half2_rn(wv.z, wv.w);
            uint2 wp = make_uint2(*(unsigned*)&w01, *(unsigned*)&w23);
            *(uint2*)&ws[row * XS_STRIDE + c * 4] = wp;
        }
        __syncthreads();
#pragma unroll
        for (int kc = 0; kc < 4; kc++) {      // four k16 sub-chunks
            unsigned a[2][4];
#pragma unroll
            for (int mi = 0; mi < 2; mi++) {
                int r0 = warp_m * 32 + mi * 16 + group;
                int base = r0 * XS_STRIDE + kc * 16 + qk;
                a[mi][0] = *(const unsigned*)&xs[base];
                a[mi][1] = *(const unsigned*)&xs[base + 8 * XS_STRIDE];
                a[mi][2] = *(const unsigned*)&xs[base + 8];
                a[mi][3] = *(const unsigned*)&xs[base + 8 * XS_STRIDE + 8];
            }
#pragma unroll
            for (int ni = 0; ni < 8; ni++) {
                int o = warp_n * 64 + ni * 8 + group;
                int wbase = o * XS_STRIDE + kc * 16 + qk;
                unsigned b0 = *(const unsigned*)&ws[wbase];
                unsigned b1 = *(const unsigned*)&ws[wbase + 8];
#pragma unroll
                for (int mi = 0; mi < 2; mi++) {
                    asm volatile(
                        "mma.sync.aligned.m16n8k16.row.col.f32.f16.f16.f32 "
                        "{%0,%1,%2,%3}, {%4,%5,%6,%7}, {%8,%9}, {%0,%1,%2,%3};"
                        : "+f"(acc[mi][ni][0]), "+f"(acc[mi][ni][1]),
                          "+f"(acc[mi][ni][2]), "+f"(acc[mi][ni][3])
                        : "r"(a[mi][0]), "r"(a[mi][1]), "r"(a[mi][2]), "r"(a[mi][3]),
                          "r"(b0), "r"(b1));
                }
            }
        }
        __syncthreads();
    }
#pragma unroll
    for (int ni = 0; ni < 8; ni++) {
        int o = warp_n * 64 + ni * 8 + qk;
        float b0 = __ldg(&bl[o]);
        float b1 = __ldg(&bl[o + 1]);
#pragma unroll
        for (int mi = 0; mi < 2; mi++) {
            int r = nb + warp_m * 32 + mi * 16 + group;
            if (r < NN)
                *(float2*)&g_hproj[r * 128 + o] =
                    make_float2(acc[mi][ni][0] + b0, acc[mi][ni][1] + b1);
            if (r + 8 < NN)
                *(float2*)&g_hproj[(r + 8) * 128 + o] =
                    make_float2(acc[mi][ni][2] + b0, acc[mi][ni][3] + b1);
        }
    }
}

// ---------------- q_agg: per-node sum of h_q over incoming edges -----------
__global__ __launch_bounds__(512) void kqagg() {
    int i = (blockIdx.x * blockDim.x + threadIdx.x) >> 5;
    int lane = threadIdx.x & 31;
    if (i >= NN) return;
    int deg = g_deg[i];
    int degE = min(deg, W);
    float4 a = make_float4(0.f, 0.f, 0.f, 0.f);
    for (int k = lane; k < degE; k += 32) {
        float4 q = g_hq[g_ell[i * W + k]];
        a.x += q.x; a.y += q.y; a.z += q.z; a.w += q.w;
    }
    if (deg > W) {  // insurance path (never taken for this input)
        int n = min(g_novf, NOVF);
        for (int t = lane; t < n; t += 32) {
            if (g_ovf_r[t] == i) {
                float4 q = g_hq[g_ovf_c[t]];
                a.x += q.x; a.y += q.y; a.z += q.z; a.w += q.w;
            }
        }
    }
#pragma unroll
    for (int off = 16; off; off >>= 1) {
        a.x += __shfl_xor_sync(0xffffffffu, a.x, off);
        a.y += __shfl_xor_sync(0xffffffffu, a.y, off);
        a.z += __shfl_xor_sync(0xffffffffu, a.z, off);
        a.w += __shfl_xor_sync(0xffffffffu, a.w, off);
    }
    if (lane == 0) g_qagg[i] = a;
}

// ---------------- kw: softmax weights per edge (passes 1-2) ----------------
__global__ __launch_bounds__(256) void kw() {
    int i = (blockIdx.x * blockDim.x + threadIdx.x) >> 5;
    int lane = threadIdx.x & 31;
    if (i >= NN) return;
    int deg = g_deg[i];
    int degE = min(deg, W);
    float4 kc = g_kact[i];

    float4 sc[4];
    float m0 = -1e30f, m1 = -1e30f, m2 = -1e30f, m3 = -1e30f;
#pragma unroll
    for (int ch = 0; ch < 4; ch++) sc[ch] = make_float4(-1e30f, -1e30f, -1e30f, -1e30f);
#pragma unroll
    for (int ch = 0; ch < 4; ch++) {
        if (ch * 32 >= degE) break;
        int k = ch * 32 + lane;
        if (k < degE) {
            int c = __ldg(&g_ell[i * W + k]);
            float4 q = g_qagg[c];
            sc[ch].x = kc.x * q.x; sc[ch].y = kc.y * q.y;
            sc[ch].z = kc.z * q.z; sc[ch].w = kc.w * q.w;
        }
        m0 = fmaxf(m0, sc[ch].x); m1 = fmaxf(m1, sc[ch].y);
        m2 = fmaxf(m2, sc[ch].z); m3 = fmaxf(m3, sc[ch].w);
    }
    if (deg > W) {  // insurance
        int n = min(g_novf, NOVF);
        for (int t = lane; t < n; t += 32) {
            if (g_ovf_r[t] == i) {
                float4 q = g_qagg[g_ovf_c[t]];
                m0 = fmaxf(m0, kc.x * q.x); m1 = fmaxf(m1, kc.y * q.y);
                m2 = fmaxf(m2, kc.z * q.z); m3 = fmaxf(m3, kc.w * q.w);
            }
        }
    }
#pragma unroll
    for (int off = 16; off; off >>= 1) {
        m0 = fmaxf(m0, __shfl_xor_sync(0xffffffffu, m0, off));
        m1 = fmaxf(m1, __shfl_xor_sync(0xffffffffu, m1, off));
        m2 = fmaxf(m2, __shfl_xor_sync(0xffffffffu, m2, off));
        m3 = fmaxf(m3, __shfl_xor_sync(0xffffffffu, m3, off));
    }

    float s0 = 0.f, s1 = 0.f, s2 = 0.f, s3 = 0.f;
#pragma unroll
    for (int ch = 0; ch < 4; ch++) {
        if (ch * 32 >= degE) break;
        const float L2E = 1.442695041f;
        __half2 ha = __floats2half2_rn((sc[ch].x - m0) * L2E, (sc[ch].y - m1) * L2E);
        __half2 hb = __floats2half2_rn((sc[ch].z - m2) * L2E, (sc[ch].w - m3) * L2E);
        unsigned ua = *(unsigned*)&ha, ub = *(unsigned*)&hb;
        unsigned ra, rb;
        asm("ex2.approx.f16x2 %0, %1;" : "=r"(ra) : "r"(ua));
        asm("ex2.approx.f16x2 %0, %1;" : "=r"(rb) : "r"(ub));
        float2 ea = __half22float2(*(__half2*)&ra);
        float2 eb = __half22float2(*(__half2*)&rb);
        sc[ch].x = ea.x; sc[ch].y = ea.y; sc[ch].z = eb.x; sc[ch].w = eb.y;
        int k = ch * 32 + lane;
        if (k >= degE) sc[ch] = make_float4(0.f, 0.f, 0.f, 0.f);
        s0 += sc[ch].x; s1 += sc[ch].y; s2 += sc[ch].z; s3 += sc[ch].w;
    }
    if (deg > W) {  // insurance
        int n = min(g_novf, NOVF);
        for (int t = lane; t < n; t += 32) {
            if (g_ovf_r[t] == i) {
                float4 q = g_qagg[g_ovf_c[t]];
                s0 += __expf(kc.x * q.x - m0); s1 += __expf(kc.y * q.y - m1);
                s2 += __expf(kc.z * q.z - m2); s3 += __expf(kc.w * q.w - m3);
            }
        }
    }
#pragma unroll
    for (int off = 16; off; off >>= 1) {
        s0 += __shfl_xor_sync(0xffffffffu, s0, off);
        s1 += __shfl_xor_sync(0xffffffffu, s1, off);
        s2 += __shfl_xor_sync(0xffffffffu, s2, off);
        s3 += __shfl_xor_sync(0xffffffffu, s3, off);
    }
    float i0 = 0.25f / (s0 + 1e-8f);
    float i1 = 0.25f / (s1 + 1e-8f);
    float i2 = 0.25f / (s2 + 1e-8f);
    float i3 = 0.25f / (s3 + 1e-8f);

#pragma unroll
    for (int ch = 0; ch < 4; ch++) {
        if (ch * 32 >= degE) break;
        int k = ch * 32 + lane;
        if (k < degE)
            g_w[i * W + k] = sc[ch].x * i0 + sc[ch].y * i1 + sc[ch].z * i2 + sc[ch].w * i3;
    }
    if (deg > W && lane == 0) {  // insurance spill
        g_m[i] = make_float4(m0, m1, m2, m3);
        g_is[i] = make_float4(i0, i1, i2, i3);
    }
}

// ---------------- kagg: gather-aggregate, packed f32x2 FMA -----------------
__global__ __launch_bounds__(256) void kagg(float* __restrict__ out) {
    int i = (blockIdx.x * blockDim.x + threadIdx.x) >> 5;
    int lane = threadIdx.x & 31;
    if (i >= NN) return;
    int deg = g_deg[i];
    int degE = min(deg, W);

    unsigned long long acc01 = 0ull, acc23 = 0ull;  // packed f32x2 accumulators
    int full = degE & ~3;
    for (int base = 0; base < full; base += 4) {
        // uniform (all-lanes-same-address) vector loads -> HW broadcast
        int4 c4 = *(const int4*)&g_ell[i * W + base];
        float4 w4 = *(const float4*)&g_w[i * W + base];
        int cs[4] = {c4.x, c4.y, c4.z, c4.w};
        float wv[4] = {w4.x, w4.y, w4.z, w4.w};
        ulonglong2 hv[4];
#pragma unroll
        for (int t = 0; t < 4; t++)
            hv[t] = ((const ulonglong2*)g_hproj)[cs[t] * 32 + lane];
#pragma unroll
        for (int t = 0; t < 4; t++) {
            unsigned long long wp;
            asm("mov.b64 %0, {%1, %1};" : "=l"(wp) : "f"(wv[t]));
            asm("fma.rn.f32x2 %0, %1, %2, %0;" : "+l"(acc01) : "l"(hv[t].x), "l"(wp));
            asm("fma.rn.f32x2 %0, %1, %2, %0;" : "+l"(acc23) : "l"(hv[t].y), "l"(wp));
        }
    }
    float4 acc;
    asm("mov.b64 {%0, %1}, %2;" : "=f"(acc.x), "=f"(acc.y) : "l"(acc01));
    asm("mov.b64 {%0, %1}, %2;" : "=f"(acc.z), "=f"(acc.w) : "l"(acc23));
    for (int k = full; k < degE; k++) {       // remainder (<= 3 edges)
        int c = g_ell[i * W + k];
        float w = g_w[i * W + k];
        float4 hp = ((const float4*)g_hproj)[c * 32 + lane];
        acc.x = fmaf(w, hp.x, acc.x);
        acc.y = fmaf(w, hp.y, acc.y);
        acc.z = fmaf(w, hp.z, acc.z);
        acc.w = fmaf(w, hp.w, acc.w);
    }
    if (deg > W) {  // insurance: recompute weights for overflow edges
        float4 kc = g_kact[i];
        float4 mm = g_m[i];
        float4 ii = g_is[i];
        int n = min(g_novf, NOVF);
        for (int t = 0; t < n; t++) {
            if (g_ovf_r[t] == i) {
                int cc = g_ovf_c[t];
                float4 q = g_qagg[cc];
                float ww = __expf(kc.x * q.x - mm.x) * ii.x + __expf(kc.y * q.y - mm.y) * ii.y +
                           __expf(kc.z * q.z - mm.z) * ii.z + __expf(kc.w * q.w - mm.w) * ii.w;
                float4 hp = ((const float4*)g_hproj)[cc * 32 + lane];
                acc.x = fmaf(ww, hp.x, acc.x);
                acc.y = fmaf(ww, hp.y, acc.y);
                acc.z = fmaf(ww, hp.z, acc.z);
                acc.w = fmaf(ww, hp.w, acc.w);
            }
        }
    }
    float4 o;
    o.x = acc.x >= 0.f ? acc.x : NEG * acc.x;
    o.y = acc.y >= 0.f ? acc.y : NEG * acc.y;
    o.z = acc.z >= 0.f ? acc.z : NEG * acc.z;
    o.w = acc.w >= 0.f ? acc.w : NEG * acc.w;
    ((float4*)out)[i * 32 + lane] = o;

    // reset build state for the next pipeline run (replay-safe invariant)
    if (lane == 0) {
        g_deg[i] = 0;
        if (i == 0) g_novf = 0;
    }
}

// ---------------- launch: 4 launches, default stream -----------------------
extern "C" void kernel_launch(void* const* d_in, const int* in_sizes, int n_in,
                              void* d_out, int out_size) {
    const float* x  = (const float*)d_in[0];
    const int*   ei = (const int*)d_in[1];
    const float* Wq = (const float*)d_in[2];
    const float* Wk = (const float*)d_in[3];
    const float* Wl = (const float*)d_in[4];
    const float* bl = (const float*)d_in[5];
    float* out = (float*)d_out;

    kbig<<<GB + BB + PB, 256>>>(x, Wq, Wk, Wl, bl, ei);   // gemm + build + proj
    kqagg<<<(NN * 32 + 511) / 512, 512>>>();
    kw<<<(NN * 32 + 255) / 256, 256>>>();
    kagg<<<(NN * 32 + 255) / 256, 256>>>(out);
}

// round 17
// speedup vs baseline: 1.0798x; 1.0798x over previous
#include <cuda_runtime.h>
#include <cuda_fp16.h>

#define NN 50000
#define NE 1600000
#define NEG 0.2f
#define W 128           // ELL width (in-degree is Poisson(32); max ~65)
#define NOVF 65536      // overflow insurance capacity

// ---------------- scratch (device globals; no allocation allowed) ----------
// g_deg/g_novf are zero at module load and re-zeroed by kwagg's tail each run.
__device__ float4 g_hq[NN];          // per-node h_q (4 heads)
__device__ float4 g_kact[NN];        // per-node leaky(x@Wk^T)
__device__ float4 g_qagg[NN];        // per-node aggregated q
__device__ __half g_hproj[NN * 128]; // per-node x@Wl^T + bl (fp16 storage)
__device__ int    g_deg[NN];
__device__ int    g_ell[NN * W];     // ELL adjacency: cols of incoming edges
__device__ int    g_ovf_r[NOVF];
__device__ int    g_ovf_c[NOVF];
__device__ int    g_novf;

// ---------------- kbig: fused gemm + build + proj --------------------------
#define GB ((NN + 127) / 128)            // 391 gemm blocks
#define BB ((NE / 16 + 255) / 256)       // 391 build blocks
#define PB ((NN * 32 + 255) / 256)       // 6250 proj blocks
#define XS_STRIDE 72
__global__ __launch_bounds__(256) void kbig(const float* __restrict__ x,
                                            const float* __restrict__ Wq,
                                            const float* __restrict__ Wk,
                                            const float* __restrict__ Wl,
                                            const float* __restrict__ bl,
                                            const int* __restrict__ ei) {
    __shared__ __half xs[128 * XS_STRIDE];
    __shared__ __half ws[128 * XS_STRIDE];
    if (blockIdx.x >= GB + BB) {
        // ---- proj branch: h_q, k_act ----
        int bid = blockIdx.x - GB - BB;
        int w = (bid * 256 + threadIdx.x) >> 5;
        int lane = threadIdx.x & 31;
        if (w >= NN) return;
        float4 xv = ((const float4*)x)[w * 32 + lane];
        float a[8];
#pragma unroll
        for (int h = 0; h < 4; h++) {
            float4 q = ((const float4*)Wq)[h * 32 + lane];
            float4 k = ((const float4*)Wk)[h * 32 + lane];
            a[h]     = xv.x * q.x + xv.y * q.y + xv.z * q.z + xv.w * q.w;
            a[4 + h] = xv.x * k.x + xv.y * k.y + xv.z * k.z + xv.w * k.w;
        }
#pragma unroll
        for (int off = 16; off; off >>= 1) {
#pragma unroll
            for (int h = 0; h < 8; h++) a[h] += __shfl_xor_sync(0xffffffffu, a[h], off);
        }
        if (lane == 0) {
            g_hq[w] = make_float4(a[0], a[1], a[2], a[3]);
            float4 kk;
            kk.x = a[4] >= 0.f ? a[4] : NEG * a[4];
            kk.y = a[5] >= 0.f ? a[5] : NEG * a[5];
            kk.z = a[6] >= 0.f ? a[6] : NEG * a[6];
            kk.w = a[7] >= 0.f ? a[7] : NEG * a[7];
            g_kact[w] = kk;
        }
        return;
    }
    if (blockIdx.x >= GB) {
        // ---- build branch: 16 edges/thread (g_deg pre-zeroed invariant) ----
        int t = (blockIdx.x - GB) * 256 + threadIdx.x;
        int e0 = t * 16;
        if (e0 >= NE) return;
        int rr[16], cc[16], pp[16];
#pragma unroll
        for (int v = 0; v < 4; v++) {
            int4 r4 = *(const int4*)&ei[e0 + v * 4];
            int4 c4 = *(const int4*)&ei[NE + e0 + v * 4];
            rr[v * 4 + 0] = r4.x; rr[v * 4 + 1] = r4.y;
            rr[v * 4 + 2] = r4.z; rr[v * 4 + 3] = r4.w;
            cc[v * 4 + 0] = c4.x; cc[v * 4 + 1] = c4.y;
            cc[v * 4 + 2] = c4.z; cc[v * 4 + 3] = c4.w;
        }
#pragma unroll
        for (int j = 0; j < 16; j++) pp[j] = atomicAdd(&g_deg[rr[j]], 1);
#pragma unroll
        for (int j = 0; j < 16; j++) {
            if (pp[j] < W) {
                g_ell[rr[j] * W + pp[j]] = cc[j];
            } else {
                int o = atomicAdd(&g_novf, 1);
                if (o < NOVF) { g_ovf_r[o] = rr[j]; g_ovf_c[o] = cc[j]; }
            }
        }
        return;
    }
    // ---- gemm branch: HMMA fp16-in fp32-acc fp16-store ----
    int nb = blockIdx.x * 128;
    int tid = threadIdx.x;
    int wid = tid >> 5;
    int lane = tid & 31;
    int warp_m = wid & 3;
    int warp_n = wid >> 2;
    int group = lane >> 2;        // 0..7
    int qk = (lane & 3) * 2;      // 0,2,4,6

    float acc[2][8][4];
#pragma unroll
    for (int mi = 0; mi < 2; mi++)
#pragma unroll
        for (int ni = 0; ni < 8; ni++)
#pragma unroll
            for (int r = 0; r < 4; r++) acc[mi][ni][r] = 0.f;

    for (int ko = 0; ko < 2; ko++) {          // two 64-wide K chunks
#pragma unroll
        for (int it = 0; it < 8; it++) {
            int idx = tid + it * 256;          // 0..2047
            int row = idx >> 4, c = idx & 15;
            float4 v = make_float4(0.f, 0.f, 0.f, 0.f);
            if (nb + row < NN) v = ((const float4*)x)[(nb + row) * 32 + ko * 16 + c];
            __half2 h01 = __floats2half2_rn(v.x, v.y);
            __half2 h23 = __floats2half2_rn(v.z, v.w);
            uint2 pk = make_uint2(*(unsigned*)&h01, *(unsigned*)&h23);
            *(uint2*)&xs[row * XS_STRIDE + c * 4] = pk;
            float4 wv = ((const float4*)Wl)[row * 32 + ko * 16 + c];
            __half2 w01 = __floats2half2_rn(wv.x, wv.y);
            __half2 w23 = __floats2half2_rn(wv.z, wv.w);
            uint2 wp = make_uint2(*(unsigned*)&w01, *(unsigned*)&w23);
            *(uint2*)&ws[row * XS_STRIDE + c * 4] = wp;
        }
        __syncthreads();
#pragma unroll
        for (int kc = 0; kc < 4; kc++) {      // four k16 sub-chunks
            unsigned a[2][4];
#pragma unroll
            for (int mi = 0; mi < 2; mi++) {
                int r0 = warp_m * 32 + mi * 16 + group;
                int base = r0 * XS_STRIDE + kc * 16 + qk;
                a[mi][0] = *(const unsigned*)&xs[base];
                a[mi][1] = *(const unsigned*)&xs[base + 8 * XS_STRIDE];
                a[mi][2] = *(const unsigned*)&xs[base + 8];
                a[mi][3] = *(const unsigned*)&xs[base + 8 * XS_STRIDE + 8];
            }
#pragma unroll
            for (int ni = 0; ni < 8; ni++) {
                int o = warp_n * 64 + ni * 8 + group;
                int wbase = o * XS_STRIDE + kc * 16 + qk;
                unsigned b0 = *(const unsigned*)&ws[wbase];
                unsigned b1 = *(const unsigned*)&ws[wbase + 8];
#pragma unroll
                for (int mi = 0; mi < 2; mi++) {
                    asm volatile(
                        "mma.sync.aligned.m16n8k16.row.col.f32.f16.f16.f32 "
                        "{%0,%1,%2,%3}, {%4,%5,%6,%7}, {%8,%9}, {%0,%1,%2,%3};"
                        : "+f"(acc[mi][ni][0]), "+f"(acc[mi][ni][1]),
                          "+f"(acc[mi][ni][2]), "+f"(acc[mi][ni][3])
                        : "r"(a[mi][0]), "r"(a[mi][1]), "r"(a[mi][2]), "r"(a[mi][3]),
                          "r"(b0), "r"(b1));
                }
            }
        }
        __syncthreads();
    }
#pragma unroll
    for (int ni = 0; ni < 8; ni++) {
        int o = warp_n * 64 + ni * 8 + qk;
        float b0 = __ldg(&bl[o]);
        float b1 = __ldg(&bl[o + 1]);
#pragma unroll
        for (int mi = 0; mi < 2; mi++) {
            int r = nb + warp_m * 32 + mi * 16 + group;
            if (r < NN) {
                __half2 h = __floats2half2_rn(acc[mi][ni][0] + b0, acc[mi][ni][1] + b1);
                *(__half2*)&g_hproj[r * 128 + o] = h;
            }
            if (r + 8 < NN) {
                __half2 h = __floats2half2_rn(acc[mi][ni][2] + b0, acc[mi][ni][3] + b1);
                *(__half2*)&g_hproj[(r + 8) * 128 + o] = h;
            }
        }
    }
}

// ---------------- q_agg: per-node sum of h_q over incoming edges -----------
__global__ __launch_bounds__(512) void kqagg() {
    int i = (blockIdx.x * blockDim.x + threadIdx.x) >> 5;
    int lane = threadIdx.x & 31;
    if (i >= NN) return;
    int deg = g_deg[i];
    int degE = min(deg, W);
    float4 a = make_float4(0.f, 0.f, 0.f, 0.f);
    for (int k = lane; k < degE; k += 32) {
        float4 q = g_hq[g_ell[i * W + k]];
        a.x += q.x; a.y += q.y; a.z += q.z; a.w += q.w;
    }
    if (deg > W) {  // insurance path (never taken for this input)
        int n = min(g_novf, NOVF);
        for (int t = lane; t < n; t += 32) {
            if (g_ovf_r[t] == i) {
                float4 q = g_hq[g_ovf_c[t]];
                a.x += q.x; a.y += q.y; a.z += q.z; a.w += q.w;
            }
        }
    }
#pragma unroll
    for (int off = 16; off; off >>= 1) {
        a.x += __shfl_xor_sync(0xffffffffu, a.x, off);
        a.y += __shfl_xor_sync(0xffffffffu, a.y, off);
        a.z += __shfl_xor_sync(0xffffffffu, a.z, off);
        a.w += __shfl_xor_sync(0xffffffffu, a.w, off);
    }
    if (lane == 0) g_qagg[i] = a;
}

// ---------------- kwagg: fused softmax + aggregation (smem staging) --------
__global__ __launch_bounds__(256) void kwagg(float* __restrict__ out) {
    __shared__ float sw[8 * 128];    // per-warp softmax weights
    __shared__ int   scol[8 * 128];  // per-warp neighbor cols
    int wo = (threadIdx.x >> 5) * 128;
    int i = (blockIdx.x * blockDim.x + threadIdx.x) >> 5;
    int lane = threadIdx.x & 31;
    if (i >= NN) return;
    int deg = g_deg[i];
    int degE = min(deg, W);
    float4 kc = g_kact[i];

    // pass 1: gather q_agg, scores into registers, cols into smem, seg max
    float4 sc[4];
    float m0 = -1e30f, m1 = -1e30f, m2 = -1e30f, m3 = -1e30f;
#pragma unroll
    for (int ch = 0; ch < 4; ch++) sc[ch] = make_float4(-1e30f, -1e30f, -1e30f, -1e30f);
#pragma unroll
    for (int ch = 0; ch < 4; ch++) {
        if (ch * 32 >= degE) break;
        int k = ch * 32 + lane;
        if (k < degE) {
            int c = __ldg(&g_ell[i * W + k]);
            scol[wo + k] = c;
            float4 q = g_qagg[c];
            sc[ch].x = kc.x * q.x; sc[ch].y = kc.y * q.y;
            sc[ch].z = kc.z * q.z; sc[ch].w = kc.w * q.w;
        }
        m0 = fmaxf(m0, sc[ch].x); m1 = fmaxf(m1, sc[ch].y);
        m2 = fmaxf(m2, sc[ch].z); m3 = fmaxf(m3, sc[ch].w);
    }
    if (deg > W) {  // insurance
        int n = min(g_novf, NOVF);
        for (int t = lane; t < n; t += 32) {
            if (g_ovf_r[t] == i) {
                float4 q = g_qagg[g_ovf_c[t]];
                m0 = fmaxf(m0, kc.x * q.x); m1 = fmaxf(m1, kc.y * q.y);
                m2 = fmaxf(m2, kc.z * q.z); m3 = fmaxf(m3, kc.w * q.w);
            }
        }
    }
#pragma unroll
    for (int off = 16; off; off >>= 1) {
        m0 = fmaxf(m0, __shfl_xor_sync(0xffffffffu, m0, off));
        m1 = fmaxf(m1, __shfl_xor_sync(0xffffffffu, m1, off));
        m2 = fmaxf(m2, __shfl_xor_sync(0xffffffffu, m2, off));
        m3 = fmaxf(m3, __shfl_xor_sync(0xffffffffu, m3, off));
    }

    // pass 2: exp via ex2.approx.f16x2 (args <= 0 -> results in [0,1])
    float s0 = 0.f, s1 = 0.f, s2 = 0.f, s3 = 0.f;
#pragma unroll
    for (int ch = 0; ch < 4; ch++) {
        if (ch * 32 >= degE) break;
        const float L2E = 1.442695041f;
        __half2 ha = __floats2half2_rn((sc[ch].x - m0) * L2E, (sc[ch].y - m1) * L2E);
        __half2 hb = __floats2half2_rn((sc[ch].z - m2) * L2E, (sc[ch].w - m3) * L2E);
        unsigned ua = *(unsigned*)&ha, ub = *(unsigned*)&hb;
        unsigned ra, rb;
        asm("ex2.approx.f16x2 %0, %1;" : "=r"(ra) : "r"(ua));
        asm("ex2.approx.f16x2 %0, %1;" : "=r"(rb) : "r"(ub));
        float2 ea = __half22float2(*(__half2*)&ra);
        float2 eb = __half22float2(*(__half2*)&rb);
        sc[ch].x = ea.x; sc[ch].y = ea.y; sc[ch].z = eb.x; sc[ch].w = eb.y;
        int k = ch * 32 + lane;
        if (k >= degE) sc[ch] = make_float4(0.f, 0.f, 0.f, 0.f);
        s0 += sc[ch].x; s1 += sc[ch].y; s2 += sc[ch].z; s3 += sc[ch].w;
    }
    if (deg > W) {  // insurance
        int n = min(g_novf, NOVF);
        for (int t = lane; t < n; t += 32) {
            if (g_ovf_r[t] == i) {
                float4 q = g_qagg[g_ovf_c[t]];
                s0 += __expf(kc.x * q.x - m0); s1 += __expf(kc.y * q.y - m1);
                s2 += __expf(kc.z * q.z - m2); s3 += __expf(kc.w * q.w - m3);
            }
        }
    }
#pragma unroll
    for (int off = 16; off; off >>= 1) {
        s0 += __shfl_xor_sync(0xffffffffu, s0, off);
        s1 += __shfl_xor_sync(0xffffffffu, s1, off);
        s2 += __shfl_xor_sync(0xffffffffu, s2, off);
        s3 += __shfl_xor_sync(0xffffffffu, s3, off);
    }
    float i0 = 0.25f / (s0 + 1e-8f);
    float i1 = 0.25f / (s1 + 1e-8f);
    float i2 = 0.25f / (s2 + 1e-8f);
    float i3 = 0.25f / (s3 + 1e-8f);

    // stage per-edge weights in smem
#pragma unroll
    for (int ch = 0; ch < 4; ch++) {
        if (ch * 32 >= degE) break;
        int k = ch * 32 + lane;
        if (k < degE)
            sw[wo + k] = sc[ch].x * i0 + sc[ch].y * i1 + sc[ch].z * i2 + sc[ch].w * i3;
    }
    __syncwarp();

    // pass 3: batch-8 fp16 gather with uniform smem broadcasts
    float4 acc = make_float4(0.f, 0.f, 0.f, 0.f);
    for (int base = 0; base < degE; base += 8) {
        int cnt = min(8, degE - base);
        int4 c0 = *(const int4*)&scol[wo + base];
        int4 c1 = *(const int4*)&scol[wo + base + 4];
        float4 w0 = *(const float4*)&sw[wo + base];
        float4 w1 = *(const float4*)&sw[wo + base + 4];
        int cs[8] = {c0.x, c0.y, c0.z, c0.w, c1.x, c1.y, c1.z, c1.w};
        float wv[8] = {w0.x, w0.y, w0.z, w0.w, w1.x, w1.y, w1.z, w1.w};
        uint2 hv[8];
#pragma unroll
        for (int t = 0; t < 8; t++)
            if (t < cnt) hv[t] = ((const uint2*)g_hproj)[cs[t] * 32 + lane];
#pragma unroll
        for (int t = 0; t < 8; t++) {
            if (t < cnt) {
                float2 f01 = __half22float2(*(__half2*)&hv[t].x);
                float2 f23 = __half22float2(*(__half2*)&hv[t].y);
                acc.x = fmaf(wv[t], f01.x, acc.x);
                acc.y = fmaf(wv[t], f01.y, acc.y);
                acc.z = fmaf(wv[t], f23.x, acc.z);
                acc.w = fmaf(wv[t], f23.y, acc.w);
            }
        }
    }
    if (deg > W) {  // insurance: weights recomputed from in-register m/i
        int n = min(g_novf, NOVF);
        for (int t = 0; t < n; t++) {
            if (g_ovf_r[t] == i) {
                int cc = g_ovf_c[t];
                float4 q = g_qagg[cc];
                float ww = __expf(kc.x * q.x - m0) * i0 + __expf(kc.y * q.y - m1) * i1 +
                           __expf(kc.z * q.z - m2) * i2 + __expf(kc.w * q.w - m3) * i3;
                uint2 hv = ((const uint2*)g_hproj)[cc * 32 + lane];
                float2 f01 = __half22float2(*(__half2*)&hv.x);
                float2 f23 = __half22float2(*(__half2*)&hv.y);
                acc.x = fmaf(ww, f01.x, acc.x);
                acc.y = fmaf(ww, f01.y, acc.y);
                acc.z = fmaf(ww, f23.x, acc.z);
                acc.w = fmaf(ww, f23.y, acc.w);
            }
        }
    }
    float4 o;
    o.x = acc.x >= 0.f ? acc.x : NEG * acc.x;
    o.y = acc.y >= 0.f ? acc.y : NEG * acc.y;
    o.z = acc.z >= 0.f ? acc.z : NEG * acc.z;
    o.w = acc.w >= 0.f ? acc.w : NEG * acc.w;
    ((float4*)out)[i * 32 + lane] = o;

    // reset build state for the next pipeline run (replay-safe invariant)
    if (lane == 0) {
        g_deg[i] = 0;
        if (i == 0) g_novf = 0;
    }
}

// ---------------- launch: 3 launches, default stream -----------------------
extern "C" void kernel_launch(void* const* d_in, const int* in_sizes, int n_in,
                              void* d_out, int out_size) {
    const float* x  = (const float*)d_in[0];
    const int*   ei = (const int*)d_in[1];
    const float* Wq = (const float*)d_in[2];
    const float* Wk = (const float*)d_in[3];
    const float* Wl = (const float*)d_in[4];
    const float* bl = (const float*)d_in[5];
    float* out = (float*)d_out;

    kbig<<<GB + BB + PB, 256>>>(x, Wq, Wk, Wl, bl, ei);   // gemm + build + proj
    kqagg<<<(NN * 32 + 511) / 512, 512>>>();
    kwagg<<<(NN * 32 + 255) / 256, 256>>>(out);
}